// round 9
// baseline (speedup 1.0000x reference)
#include <cuda_runtime.h>
#include <cuda_bf16.h>

#define FULL 0xFFFFFFFFu

constexpr int BATCH = 4096;
constexpr int DIM   = 32;
constexpr int N_MEM = 32;
constexpr int N_REL = 64;
constexpr int NCOL  = N_REL * DIM;   // 2048

// Static scratch (no runtime allocation allowed).
__device__ __nv_bfloat16  g_U[BATCH * NCOL];        // 16 MB bf16, LINEAR [b][n]
__device__ float          g_item[BATCH * DIM];
__device__ unsigned       g_Afrag[(BATCH / 16) * 2 * 32 * 4];   // A MMA frags
__device__ unsigned       g_Bfrag[(NCOL / 64) * 8 * 32 * 4];    // B MMA frags
__device__ float          g_Wt[DIM * DIM];
__device__ float          g_y[BATCH * DIM];

__device__ __forceinline__ float bf_lo(unsigned u) { return __uint_as_float(u << 16); }
__device__ __forceinline__ float bf_hi(unsigned u) { return __uint_as_float(u & 0xFFFF0000u); }

// Scatter one bf16 of the item vector into A-fragment layout.
__device__ __forceinline__ void afrag_store(int b, int e, float v) {
    const int mg = b >> 4, r = b & 15;
    const int h  = e >> 4, k = e & 15, kp = k >> 1;
    const int sel = ((r >> 3) & 1) + 2 * (kp >> 2);
    const int l   = (r & 7) * 4 + (kp & 3);
    const int idx = ((mg * 2 + h) * 32 + l) * 4 + sel;
    ((__nv_bfloat16*)g_Afrag)[idx * 2 + (k & 1)] = __float2bfloat16(v);
}

// ---------------------------------------------------------------- prep
__global__ void prep_kernel(const int* __restrict__ items,
                            const float* __restrict__ entity,
                            const float* __restrict__ relation,
                            const float* __restrict__ W) {
    const int i = blockIdx.x * blockDim.x + threadIdx.x;
    if (i < BATCH * DIM) {
        const int b = i >> 5, e = i & 31;
        const float v = entity[items[b] * DIM + e];
        g_item[i] = v;
        afrag_store(b, e, v);
    }
    if (i < (NCOL / 64) * 8 * 32 * 4) {
        const int nt = i >> 10, j = (i >> 7) & 7, l = (i >> 2) & 31, s = i & 3;
        const int n = nt * 64 + 8 * j + (l >> 2);
        const int r = n >> 5, e = n & 31;
        const int k0 = 2 * (l & 3) + 8 * s;
        const __nv_bfloat16 lo = __float2bfloat16(relation[r * 1024 + k0 * DIM + e]);
        const __nv_bfloat16 hi = __float2bfloat16(relation[r * 1024 + (k0 + 1) * DIM + e]);
        g_Bfrag[i] = ((unsigned)__bfloat16_as_ushort(hi) << 16) |
                     (unsigned)__bfloat16_as_ushort(lo);
    }
    if (i < DIM * DIM) {
        const int d = i >> 5, e = i & 31;
        g_Wt[e * DIM + d] = W[i];
    }
}

// ---------------------------------------------------------------- GEMM
__device__ __forceinline__ void mma16816(float c[4], const unsigned* a,
                                         unsigned b0, unsigned b1) {
    asm volatile(
        "mma.sync.aligned.m16n8k16.row.col.f32.bf16.bf16.f32 "
        "{%0,%1,%2,%3}, {%4,%5,%6,%7}, {%8,%9}, {%0,%1,%2,%3};\n"
        : "+f"(c[0]), "+f"(c[1]), "+f"(c[2]), "+f"(c[3])
        : "r"(a[0]), "r"(a[1]), "r"(a[2]), "r"(a[3]), "r"(b0), "r"(b1));
}

constexpr int GM = 128, GN = 64;
constexpr int OSTR = 144;   // bytes per sO row (128 payload + 16 pad)

__global__ void __launch_bounds__(256) gemm_kernel() {
    __shared__ __align__(16) char sO[8][16 * OSTR];   // per-warp slice, 18 KB

    const int lane = threadIdx.x & 31;
    const int warp = threadIdx.x >> 5;
    const int m0 = blockIdx.y * GM;
    const int n0 = blockIdx.x * GN;
    const int mg = blockIdx.y * 8 + warp;
    const int nt = blockIdx.x;

    // ---- ALL loads issued up front: MLP = 10 ----
    const uint4* __restrict__ Af = (const uint4*)g_Afrag;
    const uint4* __restrict__ Bf = (const uint4*)g_Bfrag;

    const uint4 qa0 = Af[(mg * 2 + 0) * 32 + lane];   // k 0-15
    const uint4 qa1 = Af[(mg * 2 + 1) * 32 + lane];   // k 16-31
    uint4 qb[8];
    #pragma unroll
    for (int j = 0; j < 8; ++j)
        qb[j] = Bf[(nt * 8 + j) * 32 + lane];

    char* __restrict__ so = sO[warp];
    #pragma unroll
    for (int j = 0; j < 8; ++j) {
        float c[4] = {0.f, 0.f, 0.f, 0.f};
        mma16816(c, (const unsigned*)&qa0, qb[j].x, qb[j].y);
        mma16816(c, (const unsigned*)&qa1, qb[j].z, qb[j].w);

        const __nv_bfloat162 p01 = __float22bfloat162_rn(make_float2(c[0], c[1]));
        const __nv_bfloat162 p23 = __float22bfloat162_rn(make_float2(c[2], c[3]));
        const int row  = lane >> 2;
        const int colb = (8 * j + 2 * (lane & 3)) * 2;
        *(__nv_bfloat162*)(so + row * OSTR + colb)       = p01;
        *(__nv_bfloat162*)(so + (row + 8) * OSTR + colb) = p23;
    }
    __syncwarp();

    // ---- coalesced copy-out of own 16x128B slice ----
    char* __restrict__ gU = (char*)g_U;
    #pragma unroll
    for (int i = 0; i < 4; ++i) {
        const int idx = lane + 32 * i;
        const int row = idx >> 3, ch = idx & 7;
        const uint4 v = *(const uint4*)(so + row * OSTR + ch * 16);
        *(uint4*)(gU + ((size_t)(m0 + warp * 16 + row) * NCOL + n0) * 2 + ch * 16) = v;
    }
}

// ---------------------------------------------------------------- attention
// 4 batch elems per 256-thread block; 2 warps per batch elem (16 memories each).
constexpr int AB = 4;

__global__ void __launch_bounds__(256) attn_kernel(
    const int* __restrict__ mem_h,
    const int* __restrict__ mem_r,
    const int* __restrict__ mem_t,
    const int* __restrict__ users,
    const float* __restrict__ entity,
    const float* __restrict__ user_table,
    float* __restrict__ out,
    int hop, int last)
{
    __shared__ float P[AB][N_MEM * 9];
    __shared__ float O[AB][2][DIM];

    const int lane = threadIdx.x & 31;
    const int warp = threadIdx.x >> 5;
    const int pair = warp >> 1;        // batch elem within block
    const int half = warp & 1;         // which 16 memories
    const int b = blockIdx.x * AB + pair;
    float* __restrict__ Pw = P[pair];

    const int base = hop * BATCH * N_MEM + b * N_MEM;
    const int hidx = mem_h[base + lane];
    const int ridx = mem_r[base + lane];
    const int tidx = mem_t[base + lane];

    const float item = g_item[b * DIM + lane];

    // ---- partial dots: this warp's 16 memories, 4 at a time ----
    const int mq = lane >> 3;
    const int c  = lane & 7;
    const __nv_bfloat16* __restrict__ Ub = g_U + (size_t)b * NCOL;

    #pragma unroll
    for (int it = 0; it < 4; ++it) {
        const int m = half * 16 + it * 4 + mq;
        const int r_i = __shfl_sync(FULL, ridx, m);
        const int h_i = __shfl_sync(FULL, hidx, m);
        const uint2 uu = *(const uint2*)(Ub + r_i * DIM + 4 * c);  // 4 bf16
        const float4 h4 = *(const float4*)(entity + h_i * DIM + 4 * c);
        Pw[m * 9 + c] = bf_lo(uu.x) * h4.x + bf_hi(uu.x) * h4.y +
                        bf_lo(uu.y) * h4.z + bf_hi(uu.y) * h4.w;
    }
    __syncthreads();

    // ---- logit[m] = row-sum (redundant in both warps of the pair) ----
    float logit = 0.f;
    #pragma unroll
    for (int j = 0; j < 8; ++j) logit += Pw[lane * 9 + j];

    // ---- softmax ----
    float mx = logit;
    #pragma unroll
    for (int off = 16; off; off >>= 1)
        mx = fmaxf(mx, __shfl_xor_sync(FULL, mx, off));
    const float ex = __expf(logit - mx);
    float denom = ex;
    #pragma unroll
    for (int off = 16; off; off >>= 1)
        denom += __shfl_xor_sync(FULL, denom, off);
    const float prob = ex / denom;

    // ---- o[d]: this warp's 16 memories (lane = d) ----
    float oh = 0.f;
    #pragma unroll 4
    for (int mm = 0; mm < 16; ++mm) {
        const int m = half * 16 + mm;
        const int t_i = __shfl_sync(FULL, tidx, m);
        const float p = __shfl_sync(FULL, prob, m);
        oh = fmaf(p, entity[t_i * DIM + lane], oh);
    }
    O[pair][half][lane] = oh;
    __syncthreads();
    const float o = O[pair][0][lane] + O[pair][1][lane];

    // ---- item' = (item + o) @ W^T (redundant in both warps) ----
    const float tmp = item + o;
    float itn = 0.f;
    #pragma unroll
    for (int e = 0; e < DIM; ++e)
        itn = fmaf(__shfl_sync(FULL, tmp, e), g_Wt[e * DIM + lane], itn);

    if (!last) {
        if (half == 0) {
            g_item[b * DIM + lane] = itn;
            g_y[b * DIM + lane] = o;
            afrag_store(b, lane, itn);        // next GEMM's A fragment
        }
    } else if (half == 0) {
        const float y = g_y[b * DIM + lane] + o
                      + user_table[users[b] * DIM + lane];
        float s = itn * y;
        #pragma unroll
        for (int off = 16; off; off >>= 1)
            s += __shfl_xor_sync(FULL, s, off);
        if (lane == 0)
            out[b] = 1.f / (1.f + __expf(-s));
    }
}

// ---------------------------------------------------------------- launch
extern "C" void kernel_launch(void* const* d_in, const int* in_sizes, int n_in,
                              void* d_out, int out_size) {
    const int*   items     = (const int*)d_in[0];
    const int*   mem_h     = (const int*)d_in[2];
    const int*   mem_r     = (const int*)d_in[3];
    const int*   mem_t     = (const int*)d_in[4];
    const int*   users     = (const int*)d_in[5];
    const float* entity    = (const float*)d_in[6];
    const float* relation  = (const float*)d_in[7];
    const float* user_tab  = (const float*)d_in[8];
    const float* W         = (const float*)d_in[9];
    float* out = (float*)d_out;

    prep_kernel<<<(BATCH * DIM + 255) / 256, 256>>>(items, entity, relation, W);

    const dim3 ggrid(NCOL / GN, BATCH / GM);   // 32 x 32
    gemm_kernel<<<ggrid, 256>>>();
    attn_kernel<<<BATCH / AB, 256>>>(mem_h, mem_r, mem_t, users,
                                     entity, user_tab, out, 0, 0);
    gemm_kernel<<<ggrid, 256>>>();
    attn_kernel<<<BATCH / AB, 256>>>(mem_h, mem_r, mem_t, users,
                                     entity, user_tab, out, 1, 1);
}

// round 10
// speedup vs baseline: 1.0624x; 1.0624x over previous
#include <cuda_runtime.h>
#include <cuda_bf16.h>

#define FULL 0xFFFFFFFFu

constexpr int BATCH = 4096;
constexpr int DIM   = 32;
constexpr int N_MEM = 32;
constexpr int N_REL = 64;
constexpr int NCOL  = N_REL * DIM;   // 2048

// Static scratch (no runtime allocation allowed).
__device__ __nv_bfloat16  g_U[BATCH * NCOL];        // 16 MB bf16, LINEAR [b][n]
__device__ float          g_item[BATCH * DIM];
__device__ unsigned       g_Afrag[(BATCH / 16) * 2 * 32 * 4];   // A MMA frags
__device__ unsigned       g_Bfrag[(NCOL / 64) * 8 * 32 * 4];    // B MMA frags
__device__ float          g_Wt[DIM * DIM];
__device__ float          g_y[BATCH * DIM];

__device__ __forceinline__ float bf_lo(unsigned u) { return __uint_as_float(u << 16); }
__device__ __forceinline__ float bf_hi(unsigned u) { return __uint_as_float(u & 0xFFFF0000u); }

// Scatter one bf16 of the item vector into A-fragment layout.
__device__ __forceinline__ void afrag_store(int b, int e, float v) {
    const int mg = b >> 4, r = b & 15;
    const int h  = e >> 4, k = e & 15, kp = k >> 1;
    const int sel = ((r >> 3) & 1) + 2 * (kp >> 2);
    const int l   = (r & 7) * 4 + (kp & 3);
    const int idx = ((mg * 2 + h) * 32 + l) * 4 + sel;
    ((__nv_bfloat16*)g_Afrag)[idx * 2 + (k & 1)] = __float2bfloat16(v);
}

// ---------------------------------------------------------------- prep
__global__ void prep_kernel(const int* __restrict__ items,
                            const float* __restrict__ entity,
                            const float* __restrict__ relation,
                            const float* __restrict__ W) {
    const int i = blockIdx.x * blockDim.x + threadIdx.x;
    if (i < BATCH * DIM) {
        const int b = i >> 5, e = i & 31;
        const float v = entity[items[b] * DIM + e];
        g_item[i] = v;
        afrag_store(b, e, v);
    }
    if (i < (NCOL / 64) * 8 * 32 * 4) {
        const int nt = i >> 10, j = (i >> 7) & 7, l = (i >> 2) & 31, s = i & 3;
        const int n = nt * 64 + 8 * j + (l >> 2);
        const int r = n >> 5, e = n & 31;
        const int k0 = 2 * (l & 3) + 8 * s;
        const __nv_bfloat16 lo = __float2bfloat16(relation[r * 1024 + k0 * DIM + e]);
        const __nv_bfloat16 hi = __float2bfloat16(relation[r * 1024 + (k0 + 1) * DIM + e]);
        g_Bfrag[i] = ((unsigned)__bfloat16_as_ushort(hi) << 16) |
                     (unsigned)__bfloat16_as_ushort(lo);
    }
    if (i < DIM * DIM) {
        const int d = i >> 5, e = i & 31;
        g_Wt[e * DIM + d] = W[i];
    }
}

// ---------------------------------------------------------------- GEMM
__device__ __forceinline__ void mma16816(float c[4], const unsigned* a,
                                         unsigned b0, unsigned b1) {
    asm volatile(
        "mma.sync.aligned.m16n8k16.row.col.f32.bf16.bf16.f32 "
        "{%0,%1,%2,%3}, {%4,%5,%6,%7}, {%8,%9}, {%0,%1,%2,%3};\n"
        : "+f"(c[0]), "+f"(c[1]), "+f"(c[2]), "+f"(c[3])
        : "r"(a[0]), "r"(a[1]), "r"(a[2]), "r"(a[3]), "r"(b0), "r"(b1));
}

constexpr int GM = 128, GN = 64;
constexpr int OSTR = 144;   // bytes per sO row (128 payload + 16 pad)

// minBlocks=3 -> ~84-reg budget: lets ptxas KEEP the 8-deep B preload (MLP~10)
__global__ void __launch_bounds__(256, 3) gemm_kernel() {
    __shared__ __align__(16) char sO[8][16 * OSTR];   // per-warp slice, 18 KB

    const int lane = threadIdx.x & 31;
    const int warp = threadIdx.x >> 5;
    const int m0 = blockIdx.y * GM;
    const int n0 = blockIdx.x * GN;
    const int mg = blockIdx.y * 8 + warp;
    const int nt = blockIdx.x;

    // ---- ALL loads issued up front ----
    const uint4* __restrict__ Af = (const uint4*)g_Afrag;
    const uint4* __restrict__ Bf = (const uint4*)g_Bfrag;

    const uint4 qa0 = Af[(mg * 2 + 0) * 32 + lane];   // k 0-15
    const uint4 qa1 = Af[(mg * 2 + 1) * 32 + lane];   // k 16-31
    uint4 qb[8];
    #pragma unroll
    for (int j = 0; j < 8; ++j)
        qb[j] = Bf[(nt * 8 + j) * 32 + lane];

    char* __restrict__ so = sO[warp];
    #pragma unroll
    for (int j = 0; j < 8; ++j) {
        float c[4] = {0.f, 0.f, 0.f, 0.f};
        mma16816(c, (const unsigned*)&qa0, qb[j].x, qb[j].y);
        mma16816(c, (const unsigned*)&qa1, qb[j].z, qb[j].w);

        const __nv_bfloat162 p01 = __float22bfloat162_rn(make_float2(c[0], c[1]));
        const __nv_bfloat162 p23 = __float22bfloat162_rn(make_float2(c[2], c[3]));
        const int row  = lane >> 2;
        const int colb = (8 * j + 2 * (lane & 3)) * 2;
        *(__nv_bfloat162*)(so + row * OSTR + colb)       = p01;
        *(__nv_bfloat162*)(so + (row + 8) * OSTR + colb) = p23;
    }
    __syncwarp();

    // ---- coalesced copy-out of own 16x128B slice ----
    char* __restrict__ gU = (char*)g_U;
    #pragma unroll
    for (int i = 0; i < 4; ++i) {
        const int idx = lane + 32 * i;
        const int row = idx >> 3, ch = idx & 7;
        const uint4 v = *(const uint4*)(so + row * OSTR + ch * 16);
        *(uint4*)(gU + ((size_t)(m0 + warp * 16 + row) * NCOL + n0) * 2 + ch * 16) = v;
    }
}

// ---------------------------------------------------------------- attention
// R8 shape: 8 batch elems per 256-thread block, 1 warp per batch elem.
constexpr int AW = 8;

__global__ void __launch_bounds__(256, 4) attn_kernel(
    const int* __restrict__ mem_h,
    const int* __restrict__ mem_r,
    const int* __restrict__ mem_t,
    const int* __restrict__ users,
    const float* __restrict__ entity,
    const float* __restrict__ user_table,
    float* __restrict__ out,
    int hop, int last)
{
    __shared__ float P[AW][N_MEM * 9];

    const int lane = threadIdx.x & 31;
    const int warp = threadIdx.x >> 5;
    const int b = blockIdx.x * AW + warp;
    float* __restrict__ Pw = P[warp];

    const int base = hop * BATCH * N_MEM + b * N_MEM;
    const int hidx = mem_h[base + lane];
    const int ridx = mem_r[base + lane];
    const int tidx = mem_t[base + lane];

    const float item = g_item[b * DIM + lane];

    // ---- partial dots: two 4-memory stages, loads batched up front ----
    const int mq = lane >> 3;
    const int c  = lane & 7;
    const __nv_bfloat16* __restrict__ Ub = g_U + (size_t)b * NCOL;

    #pragma unroll
    for (int stage = 0; stage < 2; ++stage) {
        uint2  uu[4];
        float4 h4[4];
        #pragma unroll
        for (int it = 0; it < 4; ++it) {
            const int m = stage * 16 + it * 4 + mq;
            const int r_i = __shfl_sync(FULL, ridx, m);
            const int h_i = __shfl_sync(FULL, hidx, m);
            uu[it] = *(const uint2*)(Ub + r_i * DIM + 4 * c);
            h4[it] = *(const float4*)(entity + h_i * DIM + 4 * c);
        }
        #pragma unroll
        for (int it = 0; it < 4; ++it) {
            const int m = stage * 16 + it * 4 + mq;
            Pw[m * 9 + c] = bf_lo(uu[it].x) * h4[it].x + bf_hi(uu[it].x) * h4[it].y +
                            bf_lo(uu[it].y) * h4[it].z + bf_hi(uu[it].y) * h4[it].w;
        }
    }
    __syncwarp();

    // ---- logit[m] (lane m) = sum of 8 partials ----
    float logit = 0.f;
    #pragma unroll
    for (int j = 0; j < 8; ++j) logit += Pw[lane * 9 + j];

    // ---- softmax ----
    float mx = logit;
    #pragma unroll
    for (int off = 16; off; off >>= 1)
        mx = fmaxf(mx, __shfl_xor_sync(FULL, mx, off));
    const float ex = __expf(logit - mx);
    float denom = ex;
    #pragma unroll
    for (int off = 16; off; off >>= 1)
        denom += __shfl_xor_sync(FULL, denom, off);
    const float prob = ex / denom;

    // ---- o[d] = sum_m prob[m] * t_m[d] ----
    float o = 0.f;
    #pragma unroll 8
    for (int m = 0; m < N_MEM; ++m) {
        const int t_i = __shfl_sync(FULL, tidx, m);
        const float p = __shfl_sync(FULL, prob, m);
        o = fmaf(p, entity[t_i * DIM + lane], o);
    }

    // ---- item' = (item + o) @ W^T ----
    const float tmp = item + o;
    float itn = 0.f;
    #pragma unroll
    for (int e = 0; e < DIM; ++e)
        itn = fmaf(__shfl_sync(FULL, tmp, e), g_Wt[e * DIM + lane], itn);

    if (!last) {
        g_item[b * DIM + lane] = itn;
        g_y[b * DIM + lane] = o;
        afrag_store(b, lane, itn);        // next GEMM's A fragment
    } else {
        const float y = g_y[b * DIM + lane] + o
                      + user_table[users[b] * DIM + lane];
        float s = itn * y;
        #pragma unroll
        for (int off = 16; off; off >>= 1)
            s += __shfl_xor_sync(FULL, s, off);
        if (lane == 0)
            out[b] = 1.f / (1.f + __expf(-s));
    }
}

// ---------------------------------------------------------------- launch
extern "C" void kernel_launch(void* const* d_in, const int* in_sizes, int n_in,
                              void* d_out, int out_size) {
    const int*   items     = (const int*)d_in[0];
    const int*   mem_h     = (const int*)d_in[2];
    const int*   mem_r     = (const int*)d_in[3];
    const int*   mem_t     = (const int*)d_in[4];
    const int*   users     = (const int*)d_in[5];
    const float* entity    = (const float*)d_in[6];
    const float* relation  = (const float*)d_in[7];
    const float* user_tab  = (const float*)d_in[8];
    const float* W         = (const float*)d_in[9];
    float* out = (float*)d_out;

    prep_kernel<<<(BATCH * DIM + 255) / 256, 256>>>(items, entity, relation, W);

    const dim3 ggrid(NCOL / GN, BATCH / GM);   // 32 x 32
    gemm_kernel<<<ggrid, 256>>>();
    attn_kernel<<<BATCH / AW, 256>>>(mem_h, mem_r, mem_t, users,
                                     entity, user_tab, out, 0, 0);
    gemm_kernel<<<ggrid, 256>>>();
    attn_kernel<<<BATCH / AW, 256>>>(mem_h, mem_r, mem_t, users,
                                     entity, user_tab, out, 1, 1);
}